// round 16
// baseline (speedup 1.0000x reference)
#include <cuda_runtime.h>

#define EMB   1024
#define NH    16
#define HD    64
#define SEQ   2048
#define BATCH 2
#define MTOT  (BATCH*SEQ)      // 4096
#define NQKV  (3*EMB)          // 3072

// Scratch (device globals: no allocation allowed in kernel_launch)
__device__ float g_q[BATCH*NH*SEQ*HD];
__device__ float g_k[BATCH*NH*SEQ*HD];
__device__ float g_v[BATCH*NH*SEQ*HD];
__device__ float g_attn[MTOT*EMB];
// Pre-converted (tf32-rounded, fp32 bit container) copies
__device__ float g_x[MTOT*EMB];
__device__ float g_wqkv[EMB*NQKV];
__device__ float g_wproj[EMB*EMB];

// ---------------------------------------------------------------------------
// TF32 helpers
// ---------------------------------------------------------------------------
__device__ __forceinline__ unsigned int f2tf32(float f) {
    unsigned int u;
    asm("cvt.rna.tf32.f32 %0, %1;" : "=r"(u) : "f"(f));
    return u;
}

__device__ __forceinline__ void mma_tf32(float c[4],
                                         const unsigned int a[4],
                                         const unsigned int b[2]) {
    asm volatile(
        "mma.sync.aligned.m16n8k8.row.col.f32.tf32.tf32.f32 "
        "{%0,%1,%2,%3}, {%4,%5,%6,%7}, {%8,%9}, {%0,%1,%2,%3};"
        : "+f"(c[0]), "+f"(c[1]), "+f"(c[2]), "+f"(c[3])
        : "r"(a[0]), "r"(a[1]), "r"(a[2]), "r"(a[3]),
          "r"(b[0]), "r"(b[1]));
}

__device__ __forceinline__ void cp_async16(void* smem_dst, const void* gsrc) {
    unsigned int d = (unsigned int)__cvta_generic_to_shared(smem_dst);
    asm volatile("cp.async.cg.shared.global [%0], [%1], 16;" :: "r"(d), "l"(gsrc));
}

// ldmatrix x4: four 8x8 b16 tiles == four 8x4 tf32 tiles
__device__ __forceinline__ void ldsm4(unsigned int r[4], const void* p) {
    unsigned int a = (unsigned int)__cvta_generic_to_shared(p);
    asm volatile("ldmatrix.sync.aligned.m8n8.x4.shared.b16 {%0,%1,%2,%3}, [%4];"
        : "=r"(r[0]), "=r"(r[1]), "=r"(r[2]), "=r"(r[3]) : "r"(a));
}

// ---------------------------------------------------------------------------
// Kernel 0: pre-convert X, Wqkv, Wproj to tf32 bits (one pass, memory-bound)
// ---------------------------------------------------------------------------
#define NX4 (MTOT*EMB/4)
#define NW4 (EMB*NQKV/4)
#define NP4 (EMB*EMB/4)

__global__ __launch_bounds__(256)
void cvt_kernel(const float* __restrict__ x, const float* __restrict__ wqkv,
                const float* __restrict__ wproj)
{
    int i = blockIdx.x * 256 + threadIdx.x;
    const float4* src; float4* dst; int j;
    if (i < NX4)            { src = (const float4*)x;     dst = (float4*)g_x;     j = i; }
    else if (i < NX4+NW4)   { src = (const float4*)wqkv;  dst = (float4*)g_wqkv;  j = i - NX4; }
    else if (i < NX4+NW4+NP4){ src = (const float4*)wproj; dst = (float4*)g_wproj; j = i - NX4 - NW4; }
    else return;
    float4 v = src[j];
    float4 o;
    o.x = __uint_as_float(f2tf32(v.x));
    o.y = __uint_as_float(f2tf32(v.y));
    o.z = __uint_as_float(f2tf32(v.z));
    o.w = __uint_as_float(f2tf32(v.w));
    dst[j] = o;
}

// GEMM tile strides (words)
#define LDA 36
#define LDB 136
#define STAGE_W (128*LDA + 32*LDB)            // 8960 words per stage
#define GEMM_SMEM (3 * STAGE_W * 4)           // 107520 B
#define NCH (EMB / 32)                        // 32 K-chunks

// ---------------------------------------------------------------------------
// Kernel 1: QKV = X @ Wqkv, TF32 mma + cp.async 3-stage + ldmatrix A-frags,
// with 1 CTA/SM (255-reg budget) and double-buffered FRAGMENT prefetch:
// ks+1 fragments are loaded before ks's mmas issue, hiding LDS latency.
// Fused RoPE; writes q (scaled), k, v tf32-rounded to [B,H,T,D].
// ---------------------------------------------------------------------------
__global__ __launch_bounds__(256, 1)
void qkv_rope_kernel(const float* __restrict__ cp, const float* __restrict__ snp)
{
    extern __shared__ float smf[];

    const int tid  = threadIdx.x;
    const int lane = tid & 31;
    const int warp = tid >> 5;
    const int g = lane >> 2, c = lane & 3;
    const int m_base = (warp & 1) * 64;
    const int n_base = (warp >> 1) * 32;
    const int m0 = blockIdx.y * 128;
    const int n0 = blockIdx.x * 128;

    const int rA = ((lane >> 3) & 1) * 8 + (lane & 7);
    const int cA = (lane >> 4) * 4;

    float acc[4][4][4];
#pragma unroll
    for (int i = 0; i < 4; i++)
#pragma unroll
        for (int j = 0; j < 4; j++)
#pragma unroll
            for (int r = 0; r < 4; r++) acc[i][j][r] = 0.f;

    const int arow = tid >> 3, ac4 = (tid & 7) * 4;
    const int brow = tid >> 5, bc4 = (tid & 31) * 4;

    auto issue = [&](int ch) {
        if (ch < NCH) {
            float* stA = smf + (ch % 3) * STAGE_W;
            float* stB = stA + 128 * LDA;
            int k0 = ch * 32;
#pragma unroll
            for (int it = 0; it < 4; it++) {
                int row = arow + it * 32;
                cp_async16(&stA[row * LDA + ac4],
                           &g_x[(size_t)(m0 + row) * EMB + k0 + ac4]);
            }
#pragma unroll
            for (int it = 0; it < 4; it++) {
                int row = brow + it * 8;
                cp_async16(&stB[row * LDB + bc4],
                           &g_wqkv[(size_t)(k0 + row) * NQKV + n0 + bc4]);
            }
        }
        asm volatile("cp.async.commit_group;");
    };

    issue(0);
    issue(1);

    for (int ch = 0; ch < NCH; ch++) {
        asm volatile("cp.async.wait_group 1;");
        __syncthreads();
        issue(ch + 2);

        const float* stA = smf + (ch % 3) * STAGE_W;
        const float* stB = stA + 128 * LDA;

        unsigned int a[2][4][4], b[2][4][2];

        auto load_frags = [&](int ks, int buf) {
#pragma unroll
            for (int mf = 0; mf < 4; mf++)
                ldsm4(a[buf][mf], &stA[(m_base + mf * 16 + rA) * LDA + ks * 8 + cA]);
#pragma unroll
            for (int nf = 0; nf < 4; nf++) {
                const float* pb = &stB[(ks * 8 + c) * LDB + n_base + nf * 8 + g];
                b[buf][nf][0] = __float_as_uint(pb[0]);
                b[buf][nf][1] = __float_as_uint(pb[4 * LDB]);
            }
        };

        load_frags(0, 0);
#pragma unroll
        for (int ks = 0; ks < 4; ks++) {
            int cur = ks & 1, nxt = cur ^ 1;
            if (ks < 3) load_frags(ks + 1, nxt);
#pragma unroll
            for (int mf = 0; mf < 4; mf++)
#pragma unroll
                for (int nf = 0; nf < 4; nf++)
                    mma_tf32(acc[mf][nf], a[cur][mf], b[cur][nf]);
        }
    }

    // Epilogue: RoPE + tf32-round + scatter (q pre-scaled by 1/8)
#pragma unroll
    for (int mf = 0; mf < 4; mf++) {
#pragma unroll
        for (int half = 0; half < 2; half++) {
            int row = m0 + m_base + mf * 16 + g + half * 8;
            int b_ = row >> 11;
            int t_ = row & (SEQ - 1);
#pragma unroll
            for (int nf = 0; nf < 4; nf++) {
                int col = n0 + n_base + nf * 8 + c * 2;
                float v0 = acc[mf][nf][half * 2 + 0];
                float v1 = acc[mf][nf][half * 2 + 1];
                int seg = col >> 10;
                int jc  = col & 1023;
                int h = jc >> 6, d = jc & 63;
                float* dst = (seg == 0) ? g_q : (seg == 1) ? g_k : g_v;
                int idx = ((b_ * NH + h) * SEQ + t_) * HD + d;
                float rx, ry;
                if (seg < 2) {
                    float cc = cp [t_ * (HD / 2) + (d >> 1)];
                    float ss = snp[t_ * (HD / 2) + (d >> 1)];
                    rx = v0 * cc - v1 * ss;
                    ry = v0 * ss + v1 * cc;
                    if (seg == 0) { rx *= 0.125f; ry *= 0.125f; }
                } else {
                    rx = v0; ry = v1;
                }
                float2 o2;
                o2.x = __uint_as_float(f2tf32(rx));
                o2.y = __uint_as_float(f2tf32(ry));
                *(float2*)&dst[idx] = o2;
            }
        }
    }
}

// ---------------------------------------------------------------------------
// Kernel 2: causal flash attention (round-9 proven version, untouched)
// ---------------------------------------------------------------------------
#define LDQ 68
#define LDK 68
#define LDV 72
#define KV_W (64*LDK + 64*LDV)                       // 8960 words per buffer
#define ATTN_SMEM ((64*LDQ + 2*KV_W) * 4)            // 89088 B

__global__ __launch_bounds__(128)
void attn_kernel()
{
    extern __shared__ float smf[];
    float* sq = smf;                                  // Q, then P (aliased)

    const int qt = gridDim.x - 1 - blockIdx.x;        // big tiles first
    const int bh = blockIdx.y;
    const float* Qb = g_q + (size_t)bh * SEQ * HD;
    const float* Kb = g_k + (size_t)bh * SEQ * HD;
    const float* Vb = g_v + (size_t)bh * SEQ * HD;

    const int tid  = threadIdx.x;
    const int lane = tid & 31;
    const int warp = tid >> 5;
    const int g = lane >> 2, c = lane & 3;
    const int rw = warp * 16;
    const int rA = ((lane >> 3) & 1) * 8 + (lane & 7);
    const int cA = (lane >> 4) * 4;
    const int rB = ((lane >> 4) & 1) * 8 + (lane & 7);
    const int cB = ((lane >> 3) & 1) * 4;

    auto skb = [&](int b) { return smf + 64 * LDQ + b * KV_W; };
    auto svb = [&](int b) { return smf + 64 * LDQ + b * KV_W + 64 * LDK; };

    auto issue_kv = [&](int kt, int b) {
        if (kt <= qt) {
            float* dk = skb(b);
            float* dv = svb(b);
#pragma unroll
            for (int it = 0; it < 8; it++) {
                int idx = tid + it * 128;
                int row = idx >> 4, c4 = (idx & 15) * 4;
                cp_async16(&dk[row * LDK + c4], &Kb[(size_t)(kt * 64 + row) * HD + c4]);
                cp_async16(&dv[row * LDV + c4], &Vb[(size_t)(kt * 64 + row) * HD + c4]);
            }
        }
        asm volatile("cp.async.commit_group;");
    };

#pragma unroll
    for (int it = 0; it < 8; it++) {
        int idx = tid + it * 128;
        int row = idx >> 4, c4 = (idx & 15) * 4;
        cp_async16(&sq[row * LDQ + c4], &Qb[(size_t)(qt * 64 + row) * HD + c4]);
    }
    issue_kv(0, 0);

    unsigned int qf[8][4];
    float oacc[8][4];
#pragma unroll
    for (int df = 0; df < 8; df++)
#pragma unroll
        for (int r = 0; r < 4; r++) oacc[df][r] = 0.f;
    float mi0 = -1e30f, mi1 = -1e30f, li0 = 0.f, li1 = 0.f;

    for (int kt = 0; kt <= qt; kt++) {
        asm volatile("cp.async.wait_group 0;");
        __syncthreads();
        if (kt == 0) {
#pragma unroll
            for (int kf = 0; kf < 8; kf++)
                ldsm4(qf[kf], &sq[(rw + rA) * LDQ + kf * 8 + cA]);
            __syncthreads();   // sq now reusable as P buffer
        }
        issue_kv(kt + 1, (kt + 1) & 1);

        const float* sk = skb(kt & 1);
        const float* sv = svb(kt & 1);

        float sacc[8][4];
#pragma unroll
        for (int nf = 0; nf < 8; nf++)
#pragma unroll
            for (int r = 0; r < 4; r++) sacc[nf][r] = 0.f;

#pragma unroll
        for (int kf = 0; kf < 8; kf++) {
            unsigned int bF[4][4];
#pragma unroll
            for (int p = 0; p < 4; p++)
                ldsm4(bF[p], &sk[(p * 16 + rB) * LDK + kf * 8 + cB]);
#pragma unroll
            for (int nf = 0; nf < 8; nf++) {
                unsigned int b2[2] = { bF[nf >> 1][(nf & 1) * 2],
                                       bF[nf >> 1][(nf & 1) * 2 + 1] };
                mma_tf32(sacc[nf], qf[kf], b2);
            }
        }

        if (kt == qt) {
            int r0 = rw + g, r1 = rw + g + 8;
#pragma unroll
            for (int nf = 0; nf < 8; nf++) {
                int col0 = nf * 8 + 2 * c, col1 = col0 + 1;
                if (col0 > r0) sacc[nf][0] = -1e30f;
                if (col1 > r0) sacc[nf][1] = -1e30f;
                if (col0 > r1) sacc[nf][2] = -1e30f;
                if (col1 > r1) sacc[nf][3] = -1e30f;
            }
        }

        float m0 = -1e30f, m1 = -1e30f;
#pragma unroll
        for (int nf = 0; nf < 8; nf++) {
            m0 = fmaxf(m0, fmaxf(sacc[nf][0], sacc[nf][1]));
            m1 = fmaxf(m1, fmaxf(sacc[nf][2], sacc[nf][3]));
        }
        m0 = fmaxf(m0, __shfl_xor_sync(0xffffffffu, m0, 1));
        m0 = fmaxf(m0, __shfl_xor_sync(0xffffffffu, m0, 2));
        m1 = fmaxf(m1, __shfl_xor_sync(0xffffffffu, m1, 1));
        m1 = fmaxf(m1, __shfl_xor_sync(0xffffffffu, m1, 2));
        float mn0 = fmaxf(mi0, m0), mn1 = fmaxf(mi1, m1);
        float al0 = __expf(mi0 - mn0), al1 = __expf(mi1 - mn1);
        mi0 = mn0; mi1 = mn1;

        float rs0 = 0.f, rs1 = 0.f;
#pragma unroll
        for (int nf = 0; nf < 8; nf++) {
            sacc[nf][0] = __expf(sacc[nf][0] - mn0);
            sacc[nf][1] = __expf(sacc[nf][1] - mn0);
            sacc[nf][2] = __expf(sacc[nf][2] - mn1);
            sacc[nf][3] = __expf(sacc[nf][3] - mn1);
            rs0 += sacc[nf][0] + sacc[nf][1];
            rs1 += sacc[nf][2] + sacc[nf][3];
        }
        rs0 += __shfl_xor_sync(0xffffffffu, rs0, 1);
        rs0 += __shfl_xor_sync(0xffffffffu, rs0, 2);
        rs1 += __shfl_xor_sync(0xffffffffu, rs1, 1);
        rs1 += __shfl_xor_sync(0xffffffffu, rs1, 2);
        li0 = li0 * al0 + rs0;
        li1 = li1 * al1 + rs1;
#pragma unroll
        for (int df = 0; df < 8; df++) {
            oacc[df][0] *= al0; oacc[df][1] *= al0;
            oacc[df][2] *= al1; oacc[df][3] *= al1;
        }

#pragma unroll
        for (int nf = 0; nf < 8; nf++) {
            sq[(rw + g)     * LDQ + nf * 8 + 2 * c]     = __uint_as_float(f2tf32(sacc[nf][0]));
            sq[(rw + g)     * LDQ + nf * 8 + 2 * c + 1] = __uint_as_float(f2tf32(sacc[nf][1]));
            sq[(rw + g + 8) * LDQ + nf * 8 + 2 * c]     = __uint_as_float(f2tf32(sacc[nf][2]));
            sq[(rw + g + 8) * LDQ + nf * 8 + 2 * c + 1] = __uint_as_float(f2tf32(sacc[nf][3]));
        }
        __syncwarp();

#pragma unroll
        for (int jf = 0; jf < 8; jf++) {
            unsigned int pa[4];
            ldsm4(pa, &sq[(rw + rA) * LDQ + jf * 8 + cA]);
#pragma unroll
            for (int df = 0; df < 8; df++) {
                unsigned int b2[2];
                const float* pv = &sv[(jf * 8 + c) * LDV + df * 8 + g];
                b2[0] = __float_as_uint(pv[0]);
                b2[1] = __float_as_uint(pv[4 * LDV]);
                mma_tf32(oacc[df], pa, b2);
            }
        }
    }

    const int b_ = bh >> 4, h = bh & 15;
    const float inv0 = 1.f / li0, inv1 = 1.f / li1;
    const int t0 = qt * 64 + rw + g, t1 = t0 + 8;
#pragma unroll
    for (int df = 0; df < 8; df++) {
        int col = h * HD + df * 8 + 2 * c;
        float2 o0, o1;
        o0.x = __uint_as_float(f2tf32(oacc[df][0] * inv0));
        o0.y = __uint_as_float(f2tf32(oacc[df][1] * inv0));
        o1.x = __uint_as_float(f2tf32(oacc[df][2] * inv1));
        o1.y = __uint_as_float(f2tf32(oacc[df][3] * inv1));
        *(float2*)&g_attn[(size_t)(b_ * SEQ + t0) * EMB + col] = o0;
        *(float2*)&g_attn[(size_t)(b_ * SEQ + t1) * EMB + col] = o1;
    }
}

// ---------------------------------------------------------------------------
// Kernel 3: out = attn @ Wproj + bproj, TF32 mma, 1 CTA/SM + frag prefetch
// ---------------------------------------------------------------------------
__global__ __launch_bounds__(256, 1)
void proj_kernel(const float* __restrict__ bias, float* __restrict__ out)
{
    extern __shared__ float smf[];

    const int tid  = threadIdx.x;
    const int lane = tid & 31;
    const int warp = tid >> 5;
    const int g = lane >> 2, c = lane & 3;
    const int m_base = (warp & 1) * 64;
    const int n_base = (warp >> 1) * 32;
    const int m0 = blockIdx.y * 128;
    const int n0 = blockIdx.x * 128;

    const int rA = ((lane >> 3) & 1) * 8 + (lane & 7);
    const int cA = (lane >> 4) * 4;

    float acc[4][4][4];
#pragma unroll
    for (int i = 0; i < 4; i++)
#pragma unroll
        for (int j = 0; j < 4; j++)
#pragma unroll
            for (int r = 0; r < 4; r++) acc[i][j][r] = 0.f;

    const int arow = tid >> 3, ac4 = (tid & 7) * 4;
    const int brow = tid >> 5, bc4 = (tid & 31) * 4;

    auto issue = [&](int ch) {
        if (ch < NCH) {
            float* stA = smf + (ch % 3) * STAGE_W;
            float* stB = stA + 128 * LDA;
            int k0 = ch * 32;
#pragma unroll
            for (int it = 0; it < 4; it++) {
                int row = arow + it * 32;
                cp_async16(&stA[row * LDA + ac4],
                           &g_attn[(size_t)(m0 + row) * EMB + k0 + ac4]);
            }
#pragma unroll
            for (int it = 0; it < 4; it++) {
                int row = brow + it * 8;
                cp_async16(&stB[row * LDB + bc4],
                           &g_wproj[(size_t)(k0 + row) * EMB + n0 + bc4]);
            }
        }
        asm volatile("cp.async.commit_group;");
    };

    issue(0);
    issue(1);

    for (int ch = 0; ch < NCH; ch++) {
        asm volatile("cp.async.wait_group 1;");
        __syncthreads();
        issue(ch + 2);

        const float* stA = smf + (ch % 3) * STAGE_W;
        const float* stB = stA + 128 * LDA;

        unsigned int a[2][4][4], b[2][4][2];

        auto load_frags = [&](int ks, int buf) {
#pragma unroll
            for (int mf = 0; mf < 4; mf++)
                ldsm4(a[buf][mf], &stA[(m_base + mf * 16 + rA) * LDA + ks * 8 + cA]);
#pragma unroll
            for (int nf = 0; nf < 4; nf++) {
                const float* pb = &stB[(ks * 8 + c) * LDB + n_base + nf * 8 + g];
                b[buf][nf][0] = __float_as_uint(pb[0]);
                b[buf][nf][1] = __float_as_uint(pb[4 * LDB]);
            }
        };

        load_frags(0, 0);
#pragma unroll
        for (int ks = 0; ks < 4; ks++) {
            int cur = ks & 1, nxt = cur ^ 1;
            if (ks < 3) load_frags(ks + 1, nxt);
#pragma unroll
            for (int mf = 0; mf < 4; mf++)
#pragma unroll
                for (int nf = 0; nf < 4; nf++)
                    mma_tf32(acc[mf][nf], a[cur][mf], b[cur][nf]);
        }
    }

#pragma unroll
    for (int mf = 0; mf < 4; mf++) {
#pragma unroll
        for (int half = 0; half < 2; half++) {
            int row = m0 + m_base + mf * 16 + g + half * 8;
#pragma unroll
            for (int nf = 0; nf < 4; nf++) {
                int col = n0 + n_base + nf * 8 + c * 2;
                float2 o2;
                o2.x = acc[mf][nf][half * 2 + 0] + bias[col + 0];
                o2.y = acc[mf][nf][half * 2 + 1] + bias[col + 1];
                *(float2*)&out[(size_t)row * EMB + col] = o2;
            }
        }
    }
}

// ---------------------------------------------------------------------------
extern "C" void kernel_launch(void* const* d_in, const int* in_sizes, int n_in,
                              void* d_out, int out_size)
{
    const float* x     = (const float*)d_in[0];
    const float* Wqkv  = (const float*)d_in[1];
    const float* Wproj = (const float*)d_in[2];
    const float* bproj = (const float*)d_in[3];
    const float* cosp  = (const float*)d_in[4];
    const float* sinp  = (const float*)d_in[5];
    float* out = (float*)d_out;

    cudaFuncSetAttribute(qkv_rope_kernel,
                         cudaFuncAttributeMaxDynamicSharedMemorySize, GEMM_SMEM);
    cudaFuncSetAttribute(attn_kernel,
                         cudaFuncAttributeMaxDynamicSharedMemorySize, ATTN_SMEM);
    cudaFuncSetAttribute(proj_kernel,
                         cudaFuncAttributeMaxDynamicSharedMemorySize, GEMM_SMEM);

    cvt_kernel<<<(NX4 + NW4 + NP4 + 255) / 256, 256>>>(x, Wqkv, Wproj);
    qkv_rope_kernel<<<dim3(NQKV / 128, MTOT / 128), 256, GEMM_SMEM>>>(cosp, sinp);
    attn_kernel<<<dim3(SEQ / 64, BATCH * NH), 128, ATTN_SMEM>>>();
    proj_kernel<<<dim3(EMB / 128, MTOT / 128), 256, GEMM_SMEM>>>(bproj, out);
}

// round 17
// speedup vs baseline: 1.0651x; 1.0651x over previous
#include <cuda_runtime.h>

#define EMB   1024
#define NH    16
#define HD    64
#define SEQ   2048
#define BATCH 2
#define MTOT  (BATCH*SEQ)      // 4096
#define NQKV  (3*EMB)          // 3072

// Scratch (device globals: no allocation allowed in kernel_launch)
__device__ float g_q[BATCH*NH*SEQ*HD];
__device__ float g_k[BATCH*NH*SEQ*HD];
__device__ float g_v[BATCH*NH*SEQ*HD];
__device__ float g_attn[MTOT*EMB];
// Pre-converted (tf32-rounded, fp32 bit container) copies
__device__ float g_x[MTOT*EMB];
__device__ float g_wqkv[EMB*NQKV];
__device__ float g_wproj[EMB*EMB];

// ---------------------------------------------------------------------------
// TF32 helpers
// ---------------------------------------------------------------------------
__device__ __forceinline__ unsigned int f2tf32(float f) {
    unsigned int u;
    asm("cvt.rna.tf32.f32 %0, %1;" : "=r"(u) : "f"(f));
    return u;
}

__device__ __forceinline__ void mma_tf32(float c[4],
                                         const unsigned int a[4],
                                         const unsigned int b[2]) {
    asm volatile(
        "mma.sync.aligned.m16n8k8.row.col.f32.tf32.tf32.f32 "
        "{%0,%1,%2,%3}, {%4,%5,%6,%7}, {%8,%9}, {%0,%1,%2,%3};"
        : "+f"(c[0]), "+f"(c[1]), "+f"(c[2]), "+f"(c[3])
        : "r"(a[0]), "r"(a[1]), "r"(a[2]), "r"(a[3]),
          "r"(b[0]), "r"(b[1]));
}

__device__ __forceinline__ void cp_async16(void* smem_dst, const void* gsrc) {
    unsigned int d = (unsigned int)__cvta_generic_to_shared(smem_dst);
    asm volatile("cp.async.cg.shared.global [%0], [%1], 16;" :: "r"(d), "l"(gsrc));
}

// ldmatrix x4: four 8x8 b16 tiles == four 8x4 tf32 tiles
__device__ __forceinline__ void ldsm4(unsigned int r[4], const void* p) {
    unsigned int a = (unsigned int)__cvta_generic_to_shared(p);
    asm volatile("ldmatrix.sync.aligned.m8n8.x4.shared.b16 {%0,%1,%2,%3}, [%4];"
        : "=r"(r[0]), "=r"(r[1]), "=r"(r[2]), "=r"(r[3]) : "r"(a));
}

// ---------------------------------------------------------------------------
// Kernel 0: pre-convert X, Wqkv, Wproj to tf32 bits (one pass, memory-bound)
// ---------------------------------------------------------------------------
#define NX4 (MTOT*EMB/4)
#define NW4 (EMB*NQKV/4)
#define NP4 (EMB*EMB/4)

__global__ __launch_bounds__(256)
void cvt_kernel(const float* __restrict__ x, const float* __restrict__ wqkv,
                const float* __restrict__ wproj)
{
    int i = blockIdx.x * 256 + threadIdx.x;
    const float4* src; float4* dst; int j;
    if (i < NX4)            { src = (const float4*)x;     dst = (float4*)g_x;     j = i; }
    else if (i < NX4+NW4)   { src = (const float4*)wqkv;  dst = (float4*)g_wqkv;  j = i - NX4; }
    else if (i < NX4+NW4+NP4){ src = (const float4*)wproj; dst = (float4*)g_wproj; j = i - NX4 - NW4; }
    else return;
    float4 v = src[j];
    float4 o;
    o.x = __uint_as_float(f2tf32(v.x));
    o.y = __uint_as_float(f2tf32(v.y));
    o.z = __uint_as_float(f2tf32(v.z));
    o.w = __uint_as_float(f2tf32(v.w));
    dst[j] = o;
}

// GEMM tile strides (words)
#define LDA 36
#define LDB 136
#define STAGE_W (128*LDA + 32*LDB)            // 8960 words per stage
#define GEMM_SMEM (3 * STAGE_W * 4)           // 107520 B
#define NCH (EMB / 32)                        // 32 K-chunks

// ---------------------------------------------------------------------------
// Kernel 1: QKV = X @ Wqkv (round-9 proven version, byte-identical)
// ---------------------------------------------------------------------------
__global__ __launch_bounds__(256, 2)
void qkv_rope_kernel(const float* __restrict__ cp, const float* __restrict__ snp)
{
    extern __shared__ float smf[];

    const int tid  = threadIdx.x;
    const int lane = tid & 31;
    const int warp = tid >> 5;
    const int g = lane >> 2, c = lane & 3;
    const int m_base = (warp & 1) * 64;
    const int n_base = (warp >> 1) * 32;
    const int m0 = blockIdx.y * 128;
    const int n0 = blockIdx.x * 128;

    const int rA = ((lane >> 3) & 1) * 8 + (lane & 7);
    const int cA = (lane >> 4) * 4;

    float acc[4][4][4];
#pragma unroll
    for (int i = 0; i < 4; i++)
#pragma unroll
        for (int j = 0; j < 4; j++)
#pragma unroll
            for (int r = 0; r < 4; r++) acc[i][j][r] = 0.f;

    const int arow = tid >> 3, ac4 = (tid & 7) * 4;
    const int brow = tid >> 5, bc4 = (tid & 31) * 4;

    auto issue = [&](int ch) {
        if (ch < NCH) {
            float* stA = smf + (ch % 3) * STAGE_W;
            float* stB = stA + 128 * LDA;
            int k0 = ch * 32;
#pragma unroll
            for (int it = 0; it < 4; it++) {
                int row = arow + it * 32;
                cp_async16(&stA[row * LDA + ac4],
                           &g_x[(size_t)(m0 + row) * EMB + k0 + ac4]);
            }
#pragma unroll
            for (int it = 0; it < 4; it++) {
                int row = brow + it * 8;
                cp_async16(&stB[row * LDB + bc4],
                           &g_wqkv[(size_t)(k0 + row) * NQKV + n0 + bc4]);
            }
        }
        asm volatile("cp.async.commit_group;");
    };

    issue(0);
    issue(1);

    for (int ch = 0; ch < NCH; ch++) {
        asm volatile("cp.async.wait_group 1;");
        __syncthreads();
        issue(ch + 2);

        const float* stA = smf + (ch % 3) * STAGE_W;
        const float* stB = stA + 128 * LDA;

#pragma unroll
        for (int ks = 0; ks < 4; ks++) {
            unsigned int a[4][4], b[4][2];
#pragma unroll
            for (int mf = 0; mf < 4; mf++)
                ldsm4(a[mf], &stA[(m_base + mf * 16 + rA) * LDA + ks * 8 + cA]);
#pragma unroll
            for (int nf = 0; nf < 4; nf++) {
                const float* pb = &stB[(ks * 8 + c) * LDB + n_base + nf * 8 + g];
                b[nf][0] = __float_as_uint(pb[0]);
                b[nf][1] = __float_as_uint(pb[4 * LDB]);
            }
#pragma unroll
            for (int mf = 0; mf < 4; mf++)
#pragma unroll
                for (int nf = 0; nf < 4; nf++)
                    mma_tf32(acc[mf][nf], a[mf], b[nf]);
        }
    }

    // Epilogue: RoPE + tf32-round + scatter (q pre-scaled by 1/8)
#pragma unroll
    for (int mf = 0; mf < 4; mf++) {
#pragma unroll
        for (int half = 0; half < 2; half++) {
            int row = m0 + m_base + mf * 16 + g + half * 8;
            int b_ = row >> 11;
            int t_ = row & (SEQ - 1);
#pragma unroll
            for (int nf = 0; nf < 4; nf++) {
                int col = n0 + n_base + nf * 8 + c * 2;
                float v0 = acc[mf][nf][half * 2 + 0];
                float v1 = acc[mf][nf][half * 2 + 1];
                int seg = col >> 10;
                int jc  = col & 1023;
                int h = jc >> 6, d = jc & 63;
                float* dst = (seg == 0) ? g_q : (seg == 1) ? g_k : g_v;
                int idx = ((b_ * NH + h) * SEQ + t_) * HD + d;
                float rx, ry;
                if (seg < 2) {
                    float cc = cp [t_ * (HD / 2) + (d >> 1)];
                    float ss = snp[t_ * (HD / 2) + (d >> 1)];
                    rx = v0 * cc - v1 * ss;
                    ry = v0 * ss + v1 * cc;
                    if (seg == 0) { rx *= 0.125f; ry *= 0.125f; }
                } else {
                    rx = v0; ry = v1;
                }
                float2 o2;
                o2.x = __uint_as_float(f2tf32(rx));
                o2.y = __uint_as_float(f2tf32(ry));
                *(float2*)&dst[idx] = o2;
            }
        }
    }
}

// ---------------------------------------------------------------------------
// Kernel 2: causal flash attention, SOFTWARE-PIPELINED:
// iteration kt overlaps {S(kt+1) + softmax(kt+1) + P-store(kt+1)} with
// {alpha-apply(kt) + PV(kt)} — two independent mma bursts + MUFU chain
// hidden under PV. Two per-warp-private P buffers; pending alpha/rowsum
// registers carry softmax(kt) results to iteration kt.
// Arithmetic order per row is IDENTICAL to round-9 (same rel_err).
// ---------------------------------------------------------------------------
#define LDQ 68
#define LDK 68
#define LDV 72
#define PB_W  (64*LDQ)                          // one P buffer (Q aliases P0)
#define KV_W  (64*LDK + 64*LDV)                 // 8960 words per buffer
#define ATTN_SMEM ((2*PB_W + 2*KV_W) * 4)       // 104448 B -> 2 CTA/SM

__global__ __launch_bounds__(128)
void attn_kernel()
{
    extern __shared__ float smf[];

    const int qt = gridDim.x - 1 - blockIdx.x;        // big tiles first
    const int bh = blockIdx.y;
    const float* Qb = g_q + (size_t)bh * SEQ * HD;
    const float* Kb = g_k + (size_t)bh * SEQ * HD;
    const float* Vb = g_v + (size_t)bh * SEQ * HD;

    const int tid  = threadIdx.x;
    const int lane = tid & 31;
    const int warp = tid >> 5;
    const int g = lane >> 2, c = lane & 3;
    const int rw = warp * 16;
    const int rA = ((lane >> 3) & 1) * 8 + (lane & 7);
    const int cA = (lane >> 4) * 4;
    const int rB = ((lane >> 4) & 1) * 8 + (lane & 7);
    const int cB = ((lane >> 3) & 1) * 4;

    auto pbuf = [&](int b) { return smf + b * PB_W; };           // P0 aliases Q
    auto skb  = [&](int b) { return smf + 2 * PB_W + b * KV_W; };
    auto svb  = [&](int b) { return smf + 2 * PB_W + b * KV_W + 64 * LDK; };

    auto issue_kv = [&](int kt, int b) {
        if (kt <= qt) {
            float* dk = skb(b);
            float* dv = svb(b);
#pragma unroll
            for (int it = 0; it < 8; it++) {
                int idx = tid + it * 128;
                int row = idx >> 4, c4 = (idx & 15) * 4;
                cp_async16(&dk[row * LDK + c4], &Kb[(size_t)(kt * 64 + row) * HD + c4]);
                cp_async16(&dv[row * LDV + c4], &Vb[(size_t)(kt * 64 + row) * HD + c4]);
            }
        }
        asm volatile("cp.async.commit_group;");
    };

    // Preamble: Q into P0 region + kv(0) in one group; kv(1) second group.
    {
        float* sq = pbuf(0);
#pragma unroll
        for (int it = 0; it < 8; it++) {
            int idx = tid + it * 128;
            int row = idx >> 4, c4 = (idx & 15) * 4;
            cp_async16(&sq[row * LDQ + c4], &Qb[(size_t)(qt * 64 + row) * HD + c4]);
        }
    }
    issue_kv(0, 0);
    issue_kv(1, 1);

    asm volatile("cp.async.wait_group 1;");   // Q + kv(0) done
    __syncthreads();

    // Q fragments (each warp reads only its own rows rw..rw+15; these same
    // rows become its private P0 region afterward -> no extra barrier needed)
    unsigned int qf[8][4];
#pragma unroll
    for (int kf = 0; kf < 8; kf++)
        ldsm4(qf[kf], &pbuf(0)[(rw + rA) * LDQ + kf * 8 + cA]);

    float oacc[8][4];
#pragma unroll
    for (int df = 0; df < 8; df++)
#pragma unroll
        for (int r = 0; r < 4; r++) oacc[df][r] = 0.f;
    float mi0 = -1e30f, mi1 = -1e30f, li0 = 0.f, li1 = 0.f;
    float al0p, al1p, rs0p, rs1p;   // pending alpha / rowsum (for next PV)

    // S + softmax + P-store for one key tile `st` into pbuf(st&1).
    auto s_stage = [&](int st) {
        const float* sk = skb(st & 1);
        float sacc[8][4];
#pragma unroll
        for (int nf = 0; nf < 8; nf++)
#pragma unroll
            for (int r = 0; r < 4; r++) sacc[nf][r] = 0.f;

#pragma unroll
        for (int kf = 0; kf < 8; kf++) {
            unsigned int bF[4][4];
#pragma unroll
            for (int p = 0; p < 4; p++)
                ldsm4(bF[p], &sk[(p * 16 + rB) * LDK + kf * 8 + cB]);
#pragma unroll
            for (int nf = 0; nf < 8; nf++) {
                unsigned int b2[2] = { bF[nf >> 1][(nf & 1) * 2],
                                       bF[nf >> 1][(nf & 1) * 2 + 1] };
                mma_tf32(sacc[nf], qf[kf], b2);
            }
        }

        if (st == qt) {                // diagonal tile: causal mask (local)
            int r0 = rw + g, r1 = rw + g + 8;
#pragma unroll
            for (int nf = 0; nf < 8; nf++) {
                int col0 = nf * 8 + 2 * c, col1 = col0 + 1;
                if (col0 > r0) sacc[nf][0] = -1e30f;
                if (col1 > r0) sacc[nf][1] = -1e30f;
                if (col0 > r1) sacc[nf][2] = -1e30f;
                if (col1 > r1) sacc[nf][3] = -1e30f;
            }
        }

        float m0 = -1e30f, m1 = -1e30f;
#pragma unroll
        for (int nf = 0; nf < 8; nf++) {
            m0 = fmaxf(m0, fmaxf(sacc[nf][0], sacc[nf][1]));
            m1 = fmaxf(m1, fmaxf(sacc[nf][2], sacc[nf][3]));
        }
        m0 = fmaxf(m0, __shfl_xor_sync(0xffffffffu, m0, 1));
        m0 = fmaxf(m0, __shfl_xor_sync(0xffffffffu, m0, 2));
        m1 = fmaxf(m1, __shfl_xor_sync(0xffffffffu, m1, 1));
        m1 = fmaxf(m1, __shfl_xor_sync(0xffffffffu, m1, 2));
        float mn0 = fmaxf(mi0, m0), mn1 = fmaxf(mi1, m1);
        al0p = __expf(mi0 - mn0);
        al1p = __expf(mi1 - mn1);
        mi0 = mn0; mi1 = mn1;

        float rs0 = 0.f, rs1 = 0.f;
#pragma unroll
        for (int nf = 0; nf < 8; nf++) {
            sacc[nf][0] = __expf(sacc[nf][0] - mn0);
            sacc[nf][1] = __expf(sacc[nf][1] - mn0);
            sacc[nf][2] = __expf(sacc[nf][2] - mn1);
            sacc[nf][3] = __expf(sacc[nf][3] - mn1);
            rs0 += sacc[nf][0] + sacc[nf][1];
            rs1 += sacc[nf][2] + sacc[nf][3];
        }
        rs0 += __shfl_xor_sync(0xffffffffu, rs0, 1);
        rs0 += __shfl_xor_sync(0xffffffffu, rs0, 2);
        rs1 += __shfl_xor_sync(0xffffffffu, rs1, 1);
        rs1 += __shfl_xor_sync(0xffffffffu, rs1, 2);
        rs0p = rs0; rs1p = rs1;

        float* sp = pbuf(st & 1);
#pragma unroll
        for (int nf = 0; nf < 8; nf++) {
            float2 p0, p1;
            p0.x = __uint_as_float(f2tf32(sacc[nf][0]));
            p0.y = __uint_as_float(f2tf32(sacc[nf][1]));
            p1.x = __uint_as_float(f2tf32(sacc[nf][2]));
            p1.y = __uint_as_float(f2tf32(sacc[nf][3]));
            *(float2*)&sp[(rw + g)     * LDQ + nf * 8 + 2 * c] = p0;
            *(float2*)&sp[(rw + g + 8) * LDQ + nf * 8 + 2 * c] = p1;
        }
        __syncwarp();
    };

    // Prologue stage for kt=0 (kv(0) already synced above)
    s_stage(0);

    for (int kt = 0; kt <= qt; kt++) {
        int cb = kt & 1;
        // Save this iteration's alphas (from softmax(kt)) before s_stage
        // overwrites the pending registers with softmax(kt+1) results.
        float al0 = al0p, al1 = al1p, rs0 = rs0p, rs1 = rs1p;

        if (kt < qt) {
            asm volatile("cp.async.wait_group 0;");   // kv(kt+1) ready
            __syncthreads();
            s_stage(kt + 1);                          // S+softmax+P for kt+1
        }

        // Apply alpha(kt), update li, then PV(kt)  — same math order as r9
        li0 = li0 * al0 + rs0;
        li1 = li1 * al1 + rs1;
#pragma unroll
        for (int df = 0; df < 8; df++) {
            oacc[df][0] *= al0; oacc[df][1] *= al0;
            oacc[df][2] *= al1; oacc[df][3] *= al1;
        }

        const float* sv = svb(cb);
        const float* sp = pbuf(cb);
#pragma unroll
        for (int jf = 0; jf < 8; jf++) {
            unsigned int pa[4];
            ldsm4(pa, &sp[(rw + rA) * LDQ + jf * 8 + cA]);
#pragma unroll
            for (int df = 0; df < 8; df++) {
                unsigned int b2[2];
                const float* pv = &sv[(jf * 8 + c) * LDV + df * 8 + g];
                b2[0] = __float_as_uint(pv[0]);
                b2[1] = __float_as_uint(pv[4 * LDV]);
                mma_tf32(oacc[df], pa, b2);
            }
        }

        __syncthreads();            // all warps done reading K/V buffer cb
        issue_kv(kt + 2, cb);       // refill cb (empty commit past the end)
    }

    // Epilogue: normalize, tf32-round, write [B,T,C]
    const int b_ = bh >> 4, h = bh & 15;
    const float inv0 = 1.f / li0, inv1 = 1.f / li1;
    const int t0 = qt * 64 + rw + g, t1 = t0 + 8;
#pragma unroll
    for (int df = 0; df < 8; df++) {
        int col = h * HD + df * 8 + 2 * c;
        float2 o0, o1;
        o0.x = __uint_as_float(f2tf32(oacc[df][0] * inv0));
        o0.y = __uint_as_float(f2tf32(oacc[df][1] * inv0));
        o1.x = __uint_as_float(f2tf32(oacc[df][2] * inv1));
        o1.y = __uint_as_float(f2tf32(oacc[df][3] * inv1));
        *(float2*)&g_attn[(size_t)(b_ * SEQ + t0) * EMB + col] = o0;
        *(float2*)&g_attn[(size_t)(b_ * SEQ + t1) * EMB + col] = o1;
    }
}

// ---------------------------------------------------------------------------
// Kernel 3: out = attn @ Wproj + bproj (round-9 proven version)
// ---------------------------------------------------------------------------
__global__ __launch_bounds__(256, 2)
void proj_kernel(const float* __restrict__ bias, float* __restrict__ out)
{
    extern __shared__ float smf[];

    const int tid  = threadIdx.x;
    const int lane = tid & 31;
    const int warp = tid >> 5;
    const int g = lane >> 2, c = lane & 3;
    const int m_base = (warp & 1) * 64;
    const int n_base = (warp >> 1) * 32;
    const int m0 = blockIdx.y * 128;
    const int n0 = blockIdx.x * 128;

    const int rA = ((lane >> 3) & 1) * 8 + (lane & 7);
    const int cA = (lane >> 4) * 4;

    float acc[4][4][4];
#pragma unroll
    for (int i = 0; i < 4; i++)
#pragma unroll
        for (int j = 0; j < 4; j++)
#pragma unroll
            for (int r = 0; r < 4; r++) acc[i][j][r] = 0.f;

    const int arow = tid >> 3, ac4 = (tid & 7) * 4;
    const int brow = tid >> 5, bc4 = (tid & 31) * 4;

    auto issue = [&](int ch) {
        if (ch < NCH) {
            float* stA = smf + (ch % 3) * STAGE_W;
            float* stB = stA + 128 * LDA;
            int k0 = ch * 32;
#pragma unroll
            for (int it = 0; it < 4; it++) {
                int row = arow + it * 32;
                cp_async16(&stA[row * LDA + ac4],
                           &g_attn[(size_t)(m0 + row) * EMB + k0 + ac4]);
            }
#pragma unroll
            for (int it = 0; it < 4; it++) {
                int row = brow + it * 8;
                cp_async16(&stB[row * LDB + bc4],
                           &g_wproj[(size_t)(k0 + row) * EMB + n0 + bc4]);
            }
        }
        asm volatile("cp.async.commit_group;");
    };

    issue(0);
    issue(1);

    for (int ch = 0; ch < NCH; ch++) {
        asm volatile("cp.async.wait_group 1;");
        __syncthreads();
        issue(ch + 2);

        const float* stA = smf + (ch % 3) * STAGE_W;
        const float* stB = stA + 128 * LDA;

#pragma unroll
        for (int ks = 0; ks < 4; ks++) {
            unsigned int a[4][4], b[4][2];
#pragma unroll
            for (int mf = 0; mf < 4; mf++)
                ldsm4(a[mf], &stA[(m_base + mf * 16 + rA) * LDA + ks * 8 + cA]);
#pragma unroll
            for (int nf = 0; nf < 4; nf++) {
                const float* pb = &stB[(ks * 8 + c) * LDB + n_base + nf * 8 + g];
                b[nf][0] = __float_as_uint(pb[0]);
                b[nf][1] = __float_as_uint(pb[4 * LDB]);
            }
#pragma unroll
            for (int mf = 0; mf < 4; mf++)
#pragma unroll
                for (int nf = 0; nf < 4; nf++)
                    mma_tf32(acc[mf][nf], a[mf], b[nf]);
        }
    }

#pragma unroll
    for (int mf = 0; mf < 4; mf++) {
#pragma unroll
        for (int half = 0; half < 2; half++) {
            int row = m0 + m_base + mf * 16 + g + half * 8;
#pragma unroll
            for (int nf = 0; nf < 4; nf++) {
                int col = n0 + n_base + nf * 8 + c * 2;
                float2 o2;
                o2.x = acc[mf][nf][half * 2 + 0] + bias[col + 0];
                o2.y = acc[mf][nf][half * 2 + 1] + bias[col + 1];
                *(float2*)&out[(size_t)row * EMB + col] = o2;
            }
        }
    }
}

// ---------------------------------------------------------------------------
extern "C" void kernel_launch(void* const* d_in, const int* in_sizes, int n_in,
                              void* d_out, int out_size)
{
    const float* x     = (const float*)d_in[0];
    const float* Wqkv  = (const float*)d_in[1];
    const float* Wproj = (const float*)d_in[2];
    const float* bproj = (const float*)d_in[3];
    const float* cosp  = (const float*)d_in[4];
    const float* sinp  = (const float*)d_in[5];
    float* out = (float*)d_out;

    cudaFuncSetAttribute(qkv_rope_kernel,
                         cudaFuncAttributeMaxDynamicSharedMemorySize, GEMM_SMEM);
    cudaFuncSetAttribute(attn_kernel,
                         cudaFuncAttributeMaxDynamicSharedMemorySize, ATTN_SMEM);
    cudaFuncSetAttribute(proj_kernel,
                         cudaFuncAttributeMaxDynamicSharedMemorySize, GEMM_SMEM);

    cvt_kernel<<<(NX4 + NW4 + NP4 + 255) / 256, 256>>>(x, Wqkv, Wproj);
    qkv_rope_kernel<<<dim3(NQKV / 128, MTOT / 128), 256, GEMM_SMEM>>>(cosp, sinp);
    attn_kernel<<<dim3(SEQ / 64, BATCH * NH), 128, ATTN_SMEM>>>();
    proj_kernel<<<dim3(EMB / 128, MTOT / 128), 256, GEMM_SMEM>>>(bproj, out);
}